// round 10
// baseline (speedup 1.0000x reference)
#include <cuda_runtime.h>
#include <cstdint>
#include <math.h>
#include <float.h>

#define B_ROWS 128
#define V_COLS 128000
#define NV4 (V_COLS / 4)
#define NB 8192
#define TPB 1024
#define BPT (NB / TPB)            // 8 bins per thread
#define RANGE_LO (-40.0f)
#define DELTA 0.009765625f        // 5*2^-9, exact in fp32
#define BIN_SCL 102.4f
#define CAPP 2048
#define CAPS 2048
#define MSCALE 34359738368.0f     // 2^35
#define MSCALE_INV (1.0 / 34359738368.0)
#define MASS_MASK ((1ULL << 48) - 1ULL)

struct Misc {
    double A_bp, SpIn, p0;
    unsigned cutPkey;
    int bp, bk, nP, nC, lenP, lenM, cl;
};

__device__ __forceinline__ int bin_of(float s) {
    int j = (int)__fmul_rn(__fadd_rn(s, -RANGE_LO), BIN_SCL);
    return max(0, min(NB - 1, j));
}
__device__ __forceinline__ float upper_edge(int j) {
    return __fmaf_rn((float)(j + 1), DELTA, RANGE_LO);   // exact for all j < NB
}
// correctly-rounded fp32 x/T (Markstein; r = correctly-rounded fp32 1/T)
__device__ __forceinline__ float div_rn(float x, float T, float r) {
    float y = __fmul_rn(x, r);
    float e = __fmaf_rn(-T, y, x);
    return __fmaf_rn(e, r, y);
}
// order-preserving float<->uint maps (ascending)
__device__ __forceinline__ unsigned fmap(float x) {
    unsigned b = __float_as_uint(x);
    return (b & 0x80000000u) ? ~b : (b | 0x80000000u);
}
__device__ __forceinline__ float finv(unsigned k) {
    unsigned b = (k & 0x80000000u) ? (k & 0x7FFFFFFFu) : ~k;
    return __uint_as_float(b);
}

__global__ void __launch_bounds__(TPB, 1) sampler_kernel(
    const float* __restrict__ logits, const float* __restrict__ temps,
    const int*   __restrict__ topks,  const float* __restrict__ topps,
    const float* __restrict__ minps,  const float* __restrict__ us,
    float* __restrict__ out, int out_size)
{
    extern __shared__ unsigned char sm[];
    unsigned long long* pack = (unsigned long long*)sm;                 // NB ull = 64 KB
    double* scanD = (double*)(sm + NB * 8);                             // TPB dbl
    int*    scanI = (int*)(sm + NB * 8 + TPB * 8);                      // TPB int
    double* cumP  = (double*)(sm + NB * 8 + TPB * 8 + TPB * 4);         // CAPS dbl
    Misc*   msc   = (Misc*)(sm + NB * 8 + TPB * 8 + TPB * 4 + CAPS * 8);
    // overlays on pack[] (pack is dead after the suffix scan): 8K+16K+16K = 40K < 64K
    float*  bufP  = (float*)sm;                                         // CAPP f32
    double* bufPe = (double*)(sm + CAPP * 4);                           // CAPP dbl
    unsigned long long* bufS = (unsigned long long*)(sm + CAPP * 12);   // CAPS ull

    const int row = blockIdx.x, tid = threadIdx.x;
    const float4* L4 = (const float4*)(logits + (size_t)row * V_COLS);
    const float T = temps[row];
    const float rT = (float)(1.0 / (double)T);      // correctly-rounded fp32 1/T
    const bool has_lp = (out_size >= B_ROWS + B_ROWS * V_COLS);
    const bool has_nt = (out_size >= B_ROWS + B_ROWS * V_COLS + B_ROWS);

    // ---------- init ----------
    for (int j = tid; j < NB; j += TPB) pack[j] = 0ULL;
    if (tid == 0) {
        msc->A_bp = 0.0; msc->SpIn = 0.0; msc->p0 = 0.0;
        msc->cutPkey = 0xFFFFFFFFu;
        msc->bp = 0; msc->bk = 0; msc->nP = 0; msc->nC = 0;
        msc->lenP = 0; msc->lenM = 0; msc->cl = 0;
    }
    __syncthreads();

    // ---------- Pass B: packed histogram (count<<48 | fixed-point poly mass) ----------
    #pragma unroll 4
    for (int i = tid; i < NV4; i += TPB) {
        float4 x = L4[i];
        float xs[4] = {x.x, x.y, x.z, x.w};
        #pragma unroll
        for (int c = 0; c < 4; ++c) {
            float s = div_rn(xs[c], T, rT);
            int j = bin_of(s);
            float u = __fadd_rn(s, -upper_edge(j));
            float poly = __fmaf_rn(u, __fmaf_rn(u, __fmaf_rn(u, 0.16666667f, 0.5f), 1.0f), 1.0f);
            atomicAdd(&pack[j], (1ULL << 48) + __float2ull_rn(__fmul_rn(poly, MSCALE)));
        }
    }
    __syncthreads();

    // ---------- suffix scan (fp64 mass, counts); find straddle bins ----------
    const int base = tid * BPT;
    double locM[BPT]; int locC[BPT];
    {
        double rm = 0.0; int rc = 0;
        #pragma unroll
        for (int k = BPT - 1; k >= 0; --k) {
            unsigned long long v = pack[base + k];
            rc += (int)(v >> 48);
            rm += (double)(v & MASS_MASK) * MSCALE_INV * exp((double)upper_edge(base + k));
            locM[k] = rm; locC[k] = rc;
        }
        scanD[tid] = rm; scanI[tid] = rc;
    }
    __syncthreads();
    for (int off = 1; off < TPB; off <<= 1) {
        double dv = (tid + off < TPB) ? scanD[tid + off] : 0.0;
        int    iv = (tid + off < TPB) ? scanI[tid + off] : 0;
        __syncthreads();
        scanD[tid] += dv; scanI[tid] += iv;
        __syncthreads();
    }
    const double excM = (tid + 1 < TPB) ? scanD[tid + 1] : 0.0;
    const int    excC = (tid + 1 < TPB) ? scanI[tid + 1] : 0;
    const double Pthr = (double)topps[row] * scanD[0];
    const int    Kv   = topks[row];
    #pragma unroll
    for (int k = 0; k < BPT; ++k) {
        double sj  = locM[k] + excM;
        double sj1 = (k < BPT - 1 ? locM[k + 1] : 0.0) + excM;
        if (sj1 <= Pthr && Pthr < sj) { msc->bp = base + k; msc->A_bp = sj1; }
        int cj  = locC[k] + excC;
        int cj1 = (k < BPT - 1 ? locC[k + 1] : 0) + excC;
        if (cj1 < Kv && Kv <= cj) msc->bk = base + k;
    }
    __syncthreads();
    const int bpv = msc->bp, bkv = msc->bk;

    // ---------- Pass C: collect top-p boundary bin + sampling candidates ----------
    #pragma unroll 4
    for (int i = tid; i < NV4; i += TPB) {
        float4 x = L4[i];
        float xs[4] = {x.x, x.y, x.z, x.w};
        #pragma unroll
        for (int c = 0; c < 4; ++c) {
            float s = div_rn(xs[c], T, rT);
            int j = bin_of(s);
            if (j < bkv && j != bpv) continue;
            if (j == bpv) { int q = atomicAdd(&msc->nP, 1); if (q < CAPP) bufP[q] = s; }
            if (j >= bkv) {
                int q = atomicAdd(&msc->nC, 1);
                if (q < CAPS)
                    bufS[q] = (((unsigned long long)(~fmap(s))) << 32) | (unsigned)(4 * i + c);
            }
        }
    }
    __syncthreads();
    const int nP = min(msc->nP, CAPP);
    const int nC = min(msc->nC, CAPS);
    for (int i = tid; i < nP; i += TPB) bufPe[i] = exp((double)bufP[i]);
    __syncthreads();

    // top-p cut for LOGPROBS only: fp64 in-bin exclusive sums vs Pthr
    const double A_bp = msc->A_bp;
    for (int i = tid; i < nP; i += TPB) {
        float ti = bufP[i];
        double g = 0.0;
        for (int w = 0; w < nP; ++w) if (bufP[w] > ti) g += bufPe[w];
        if (A_bp + g <= Pthr) {
            atomicMin(&msc->cutPkey, fmap(ti));
            atomicAdd(&msc->SpIn, bufPe[i]);
        }
    }
    __syncthreads();
    const float cutP = finv(msc->cutPkey);
    const float lnS  = (float)log(A_bp + msc->SpIn);

    // ---------- bitonic sort: exact reference order (desc value, asc index) ----------
    int n2 = 1; while (n2 < nC) n2 <<= 1;
    if (n2 < 2) n2 = 2;
    for (int i = tid; i < n2; i += TPB) if (i >= nC) bufS[i] = 0xFFFFFFFFFFFFFFFFULL;
    __syncthreads();
    for (int k = 2; k <= n2; k <<= 1) {
        for (int jj = k >> 1; jj > 0; jj >>= 1) {
            for (int i = tid; i < n2; i += TPB) {
                int ix = i ^ jj;
                if (ix > i) {
                    unsigned long long a = bufS[i], b = bufS[ix];
                    if (((i & k) == 0) == (a > b)) { bufS[i] = b; bufS[ix] = a; }
                }
            }
            __syncthreads();
        }
    }

    // ---------- positional filtering (rank<K, excl-cumsum<=Pthr, p>=p0*minp) ----------
    const int i0 = tid, i1 = tid + TPB;
    double pr0 = 0.0, pr1 = 0.0;
    if (i0 < nC) pr0 = exp((double)finv(~(unsigned)(bufS[i0] >> 32)));
    if (i1 < nC) pr1 = exp((double)finv(~(unsigned)(bufS[i1] >> 32)));
    if (i0 < n2) cumP[i0] = pr0;
    if (i1 < n2) cumP[i1] = pr1;
    if (i0 == 0) msc->p0 = pr0;
    __syncthreads();
    for (int off = 1; off < n2; off <<= 1) {
        double a0 = 0.0, a1 = 0.0;
        if (i0 < n2 && i0 >= off) a0 = cumP[i0 - off];
        if (i1 < n2 && i1 >= off) a1 = cumP[i1 - off];
        __syncthreads();
        if (i0 < n2) cumP[i0] += a0;
        if (i1 < n2) cumP[i1] += a1;
        __syncthreads();
    }
    {
        const double thrM = msc->p0 * (double)minps[row];
        int lp = 0, lm = 0;
        if (i0 < nC) { lp += (cumP[i0] - pr0 <= Pthr); lm += (pr0 >= thrM); }
        if (i1 < nC) { lp += (cumP[i1] - pr1 <= Pthr); lm += (pr1 >= thrM); }
        #pragma unroll
        for (int o = 16; o; o >>= 1) {
            lp += __shfl_xor_sync(~0u, lp, o);
            lm += __shfl_xor_sync(~0u, lm, o);
        }
        if ((tid & 31) == 0) { atomicAdd(&msc->lenP, lp); atomicAdd(&msc->lenM, lm); }
    }
    __syncthreads();
    const int nKeep = max(1, min(Kv, min(msc->lenP, msc->lenM)));
    const double target = (double)us[row] * cumP[nKeep - 1];
    {
        int cl = 0;
        if (i0 < nKeep) cl += (cumP[i0] < target);
        if (i1 < nKeep) cl += (cumP[i1] < target);
        #pragma unroll
        for (int o = 16; o; o >>= 1) cl += __shfl_xor_sync(~0u, cl, o);
        if ((tid & 31) == 0) atomicAdd(&msc->cl, cl);
    }
    __syncthreads();
    if (tid == 0) {
        int si = min(msc->cl, nKeep - 1);
        unsigned long long key = bufS[si];
        out[row] = (float)(int)(key & 0xFFFFFFFFu);
        if (has_nt) {
            float stok = finv(~(unsigned)(key >> 32));
            out[B_ROWS + (size_t)B_ROWS * V_COLS + row] = stok - lnS;
        }
    }

    // ---------- Pass D: full-vocab logprobs ----------
    if (has_lp) {
        float4* O4 = (float4*)(out + B_ROWS + (size_t)row * V_COLS);
        for (int i = tid; i < NV4; i += TPB) {
            float4 x = __ldcs(&L4[i]);
            float4 o;
            float s0 = div_rn(x.x, T, rT), s1 = div_rn(x.y, T, rT);
            float s2 = div_rn(x.z, T, rT), s3 = div_rn(x.w, T, rT);
            o.x = (s0 >= cutP) ? (s0 - lnS) : -FLT_MAX;
            o.y = (s1 >= cutP) ? (s1 - lnS) : -FLT_MAX;
            o.z = (s2 >= cutP) ? (s2 - lnS) : -FLT_MAX;
            o.w = (s3 >= cutP) ? (s3 - lnS) : -FLT_MAX;
            __stcs(&O4[i], o);
        }
    }
}

extern "C" void kernel_launch(void* const* d_in, const int* in_sizes, int n_in,
                              void* d_out, int out_size) {
    const float* logits = (const float*)d_in[0];
    const float* temps  = (const float*)d_in[1];
    const int*   topks  = (const int*)d_in[2];
    const float* topps  = (const float*)d_in[3];
    const float* minps  = (const float*)d_in[4];
    const float* us     = (const float*)d_in[5];
    float* out = (float*)d_out;

    const size_t smem = NB * 8 + TPB * 8 + TPB * 4 + CAPS * 8 + 256;   // ~94.5 KB
    cudaFuncSetAttribute(sampler_kernel, cudaFuncAttributeMaxDynamicSharedMemorySize, (int)smem);
    sampler_kernel<<<B_ROWS, TPB, smem>>>(logits, temps, topks, topps, minps, us,
                                          out, out_size);
}